// round 10
// baseline (speedup 1.0000x reference)
#include <cuda_runtime.h>
#include <cuda_fp16.h>
#include <cstdint>

#define D_DIM 256
#define N_TOK 32768
#define N_CODE 2048
#define CAP 64
#define PADC 0.05f

// ---------------- scratch (static device globals) ---------------------------
__device__ __half g_xhi[N_TOK * D_DIM];   // X hi split, A-fragment order
__device__ __half g_ehi[N_CODE * D_DIM];  // E hi split, B-fragment order
__device__ float  g_embed[N_CODE * D_DIM];// E row-major
__device__ float  g_esq[N_CODE];          // ||e||^2
__device__ float  g_eln[N_CODE];          // ||e_lo||
__device__ float  g_xh2[4 * N_TOK];       // per-(chunk,token) ||x_hi||^2 partials
__device__ float  g_xl2[4 * N_TOK];       // per-(chunk,token) ||x_lo||^2 partials
__device__ int    g_cnt[N_TOK];           // candidate counts
__device__ int    g_cand[N_TOK * CAP];    // candidate code ids
__device__ int    g_idx[N_TOK];           // final indices

// ---------------- helpers ----------------------------------------------------
__device__ __forceinline__ uint32_t smem_u32(const void* p) {
    uint32_t a;
    asm("{ .reg .u64 t; cvta.to.shared.u64 t, %1; cvt.u32.u64 %0, t; }"
        : "=r"(a) : "l"(p));
    return a;
}
__device__ __forceinline__ uint32_t pack2(__half a, __half b) {
    __half2 h2 = __halves2half2(a, b);
    return *reinterpret_cast<uint32_t*>(&h2);
}

#define MBAR_INIT(a, c) asm volatile("mbarrier.init.shared.b64 [%0], %1;" :: "r"(a), "r"((uint32_t)(c)) : "memory")
#define MBAR_EXPECT_TX(a, b) asm volatile("mbarrier.arrive.expect_tx.shared.b64 _, [%0], %1;" :: "r"(a), "r"((uint32_t)(b)) : "memory")
#define MBAR_ARRIVE(a)  asm volatile("mbarrier.arrive.shared.b64 _, [%0];" :: "r"(a) : "memory")

#define MBAR_WAIT(mbar, parity) do {                                          \
    uint32_t _m = (mbar), _ph = (parity), _done;                              \
    asm volatile("{ .reg .pred p; mbarrier.try_wait.parity.acquire.cta.shared::cta.b64 p, [%1], %2; selp.b32 %0, 1, 0, p; }" \
                 : "=r"(_done) : "r"(_m), "r"(_ph) : "memory");               \
    if (!_done) {                                                             \
        asm volatile("{ .reg .pred P1; WL_%=: mbarrier.try_wait.parity.acquire.cta.shared::cta.b64 P1, [%0], %1, 0x989680; @P1 bra.uni WD_%=; bra.uni WL_%=; WD_%=: }" \
                     :: "r"(_m), "r"(_ph) : "memory");                        \
    }                                                                         \
} while (0)

#define BULK_G2S(dst, src, bytes, mbar)                                       \
    asm volatile("cp.async.bulk.shared::cluster.global.mbarrier::complete_tx::bytes [%0], [%1], %2, [%3];" \
                 :: "r"(dst), "l"(src), "r"((uint32_t)(bytes)), "r"(mbar) : "memory")

__device__ __forceinline__ void mma_f16(float* d, const uint32_t* a, const uint32_t* b) {
    asm("mma.sync.aligned.m16n8k16.row.col.f32.f16.f16.f32 "
        "{%0,%1,%2,%3}, {%4,%5,%6,%7}, {%8,%9}, {%0,%1,%2,%3};"
        : "+f"(d[0]), "+f"(d[1]), "+f"(d[2]), "+f"(d[3])
        : "r"(a[0]), "r"(a[1]), "r"(a[2]), "r"(a[3]), "r"(b[0]), "r"(b[1]));
}

// ---------------------------------------------------------------------------
// prep: blocks [0,1024): E prep (2 codes/block). Blocks [1024,2048): X split
// (smem-staged coalesced out) + norm partials + g_cnt zeroing.
// ---------------------------------------------------------------------------
__global__ void __launch_bounds__(256) prep_all_kernel(const float* __restrict__ X,
                                                       const float* __restrict__ embed_sum,
                                                       const float* __restrict__ usage) {
    if (blockIdx.x < N_CODE / 2) {
        int t = threadIdx.x;
        int k = blockIdx.x * 2 + (t >> 7);
        int tl = t & 127;
        __shared__ float wq[8], wl[8];

        float u = fmaxf(usage[k], 1e-5f);
        float2 vv = ((const float2*)embed_sum)[k * 128 + tl];
        float v0 = vv.x / u, v1 = vv.y / u;
        ((float2*)g_embed)[k * 128 + tl] = make_float2(v0, v1);

        __half h0 = __float2half_rn(v0);
        __half h1 = __float2half_rn(v1);
        float l0f = v0 - __half2float(h0), l1f = v1 - __half2float(h1);

        int d = 2 * tl;
        int pass = k >> 7, n_in = k & 127;
        int n_tile = n_in >> 3, ncol = n_in & 7;
        int ch = d >> 6, kk = d & 63, ks = kk >> 4, kc = kk & 15;
        int lane = ncol * 4 + ((kc >> 1) & 3);
        int reg = kc >> 3;
        int hbase = (pass * 4 + ch) * 8192 + ((ks * 16 + n_tile) * 32 + lane) * 4 + reg * 2;
        ((uint32_t*)g_ehi)[hbase >> 1] = pack2(h0, h1);

        float sq = v0 * v0 + v1 * v1;
        float sl = l0f * l0f + l1f * l1f;
        #pragma unroll
        for (int off = 16; off > 0; off >>= 1) {
            sq += __shfl_down_sync(0xffffffffu, sq, off);
            sl += __shfl_down_sync(0xffffffffu, sl, off);
        }
        if ((t & 31) == 0) { wq[t >> 5] = sq; wl[t >> 5] = sl; }
        __syncthreads();
        if (tl == 0) {
            int w0 = (t >> 7) * 4;
            g_esq[k] = wq[w0] + wq[w0 + 1] + wq[w0 + 2] + wq[w0 + 3];
            g_eln[k] = sqrtf(wl[w0] + wl[w0 + 1] + wl[w0 + 2] + wl[w0 + 3]);
        }
    } else {
        __shared__ uint32_t sh_hi[4096];
        __shared__ float xa_h[128], xa_l[128];
        int tile = blockIdx.x - N_CODE / 2;
        int m_block = tile >> 2, ch = tile & 3;
        int t = threadIdx.x;
        if (t < 128) { xa_h[t] = 0.f; xa_l[t] = 0.f; }
        if (t < 32) g_cnt[tile * 32 + t] = 0;
        __syncthreads();

        #pragma unroll
        for (int it = 0; it < 8; ++it) {
            int i4 = t + it * 256;
            int tok_l = i4 >> 4;
            int dl4 = i4 & 15;
            float4 x = ((const float4*)X)[(size_t)(m_block * 128 + tok_l) * 64 + ch * 16 + dl4];
            float xv[4] = {x.x, x.y, x.z, x.w};
            int m_tile = tok_l >> 4, r = tok_l & 15;
            float hs = 0.f, ls = 0.f;
            #pragma unroll
            for (int j = 0; j < 4; j += 2) {
                __half ha = __float2half_rn(xv[j]);
                __half hb = __float2half_rn(xv[j + 1]);
                float haf = __half2float(ha), hbf = __half2float(hb);
                float laf = xv[j] - haf, lbf = xv[j + 1] - hbf;
                hs += haf * haf + hbf * hbf;
                ls += laf * laf + lbf * lbf;
                int kk = dl4 * 4 + j;
                int ks = kk >> 4, kc = kk & 15;
                int lane = (r & 7) * 4 + ((kc >> 1) & 3);
                int reg = (r >> 3) | ((kc >> 3) << 1);
                int half_loc = ((ks * 8 + m_tile) * 32 + lane) * 8 + reg * 2;
                sh_hi[half_loc >> 1] = pack2(ha, hb);
            }
            atomicAdd(&xa_h[tok_l], hs);
            atomicAdd(&xa_l[tok_l], ls);
        }
        __syncthreads();

        uint4* dh = (uint4*)(((uint32_t*)g_xhi) + tile * 4096);
        const uint4* sh4 = (const uint4*)sh_hi;
        #pragma unroll
        for (int it = 0; it < 4; ++it)
            dh[t + it * 256] = sh4[t + it * 256];

        if (t < 128) {
            int tok = m_block * 128 + t;
            g_xh2[ch * N_TOK + tok] = xa_h[t];
            g_xl2[ch * N_TOK + tok] = xa_l[t];
        }
    }
}

// ---------------------------------------------------------------------------
// Stage A: hi-only fp16 mma GEMM; collect codes with d~ <= Brun + W, where
// Brun = warp-subset running min of d~ and W = 2*Umax(token) with quarter-wide
// norm maxima. O(1) work per code in the epilogue.
// ---------------------------------------------------------------------------
#define SMEM_TOTAL 119808
#define A_OFF 5120
#define B_OFF 70656

__global__ void __launch_bounds__(288, 1) stageA_kernel() {
    extern __shared__ __align__(1024) char smem[];
    uint32_t sb = smem_u32(smem);
    int tid = threadIdx.x, lane = tid & 31, wid = tid >> 5;
    int mtile = blockIdx.x >> 2, q = blockIdx.x & 3;
    int row0 = mtile * 128;

    const uint32_t AF    = sb + 0;
    const uint32_t FB[3] = {sb + 8,  sb + 16, sb + 24};
    const uint32_t EB[3] = {sb + 32, sb + 40, sb + 48};
    float* esq_s = (float*)(smem + 1024);   // [512]
    float* xhn_s = (float*)(smem + 3072);   // [128]
    float* xln_s = (float*)(smem + 3584);   // [128]
    int*   qm    = (int*)(smem + 4096);     // qm[0]=max eln, qm[1]=max en (bits)

    if (tid == 0) {
        MBAR_INIT(AF, 1);
        #pragma unroll
        for (int s = 0; s < 3; ++s) { MBAR_INIT(FB[s], 1); MBAR_INIT(EB[s], 8); }
        qm[0] = 0; qm[1] = 0;
    }
    __syncthreads();
    {
        float ml = 0.f, mn = 0.f;
        for (int i = tid; i < 512; i += 288) {
            float e2 = g_esq[q * 512 + i];
            esq_s[i] = e2;
            mn = fmaxf(mn, sqrtf(e2));
            ml = fmaxf(ml, g_eln[q * 512 + i]);
        }
        atomicMax(&qm[0], __float_as_int(ml));
        atomicMax(&qm[1], __float_as_int(mn));
    }
    if (tid < 128) {
        int tok = row0 + tid;
        xhn_s[tid] = sqrtf(g_xh2[tok] + g_xh2[N_TOK + tok] +
                           g_xh2[2 * N_TOK + tok] + g_xh2[3 * N_TOK + tok]);
        xln_s[tid] = sqrtf(g_xl2[tok] + g_xl2[N_TOK + tok] +
                           g_xl2[2 * N_TOK + tok] + g_xl2[3 * N_TOK + tok]);
    }
    __syncthreads();

    if (wid == 8) {
        if (lane == 0) {
            MBAR_EXPECT_TX(AF, 65536);
            #pragma unroll
            for (int ch = 0; ch < 4; ++ch)
                BULK_G2S(sb + A_OFF + ch * 16384,
                         &g_xhi[(mtile * 4 + ch) * 8192], 16384, AF);
            #pragma unroll 1
            for (int g = 0; g < 16; ++g) {
                int s = g % 3;
                if (g >= 3) MBAR_WAIT(EB[s], ((g / 3) + 1) & 1);
                int pass = g >> 2, ch = g & 3;
                MBAR_EXPECT_TX(FB[s], 16384);
                BULK_G2S(sb + B_OFF + s * 16384,
                         &g_ehi[((q * 4 + pass) * 4 + ch) * 8192], 16384, FB[s]);
            }
        }
    } else {
        int warp_m = wid & 3, warp_n = wid >> 2;
        int t4 = lane & 3, g4 = lane >> 2;

        float maxeln = __int_as_float(qm[0]);
        float maxen  = __int_as_float(qm[1]);

        float W[2][2], Brun[2][2];
        #pragma unroll
        for (int mt = 0; mt < 2; ++mt)
            #pragma unroll
            for (int h = 0; h < 2; ++h) {
                int tok_l = warp_m * 32 + mt * 16 + g4 + 8 * h;
                float xh = xhn_s[tok_l], xl = xln_s[tok_l];
                // W = 2*Umax; Umax = 2(xh*maxeln + xl*(maxen+2maxeln)) + PADC
                W[mt][h] = 2.f * (2.f * (xh * maxeln + xl * (maxen + 2.f * maxeln)) + PADC);
                Brun[mt][h] = 3.4e38f;
            }

        MBAR_WAIT(AF, 0);

        #pragma unroll 1
        for (int pass = 0; pass < 4; ++pass) {
            float acc[2][8][4];
            #pragma unroll
            for (int mt = 0; mt < 2; ++mt)
                #pragma unroll
                for (int nt = 0; nt < 8; ++nt)
                    #pragma unroll
                    for (int j = 0; j < 4; ++j) acc[mt][nt][j] = 0.f;

            #pragma unroll 1
            for (int ch = 0; ch < 4; ++ch) {
                int g = pass * 4 + ch;
                int s = g % 3;
                MBAR_WAIT(FB[s], (g / 3) & 1);
                const char* Ah = smem + A_OFF + ch * 16384;
                const char* Bh = smem + B_OFF + s * 16384;
                #pragma unroll
                for (int ks = 0; ks < 4; ++ks) {
                    uint32_t ah[2][4];
                    #pragma unroll
                    for (int mt = 0; mt < 2; ++mt) {
                        int off = ((ks * 8 + warp_m * 2 + mt) * 32 + lane) * 16;
                        *(uint4*)ah[mt] = *(const uint4*)(Ah + off);
                    }
                    uint32_t bh[8][2];
                    #pragma unroll
                    for (int nt = 0; nt < 8; ++nt) {
                        int off = ((ks * 16 + warp_n * 8 + nt) * 32 + lane) * 8;
                        *(uint2*)bh[nt] = *(const uint2*)(Bh + off);
                    }
                    #pragma unroll
                    for (int mt = 0; mt < 2; ++mt)
                        #pragma unroll
                        for (int nt = 0; nt < 8; ++nt)
                            mma_f16(acc[mt][nt], ah[mt], bh[nt]);
                }
                if (lane == 0) MBAR_ARRIVE(EB[s]);
            }

            // ---- phase 1: Brun = min d~ (1 FMA + mins per code) -------------
            float m1[2][2] = {{3.4e38f, 3.4e38f}, {3.4e38f, 3.4e38f}};
            #pragma unroll
            for (int nt = 0; nt < 8; ++nt) {
                int cl = pass * 128 + warp_n * 64 + nt * 8 + 2 * t4;
                float e0 = esq_s[cl], e1 = esq_s[cl + 1];
                #pragma unroll
                for (int mt = 0; mt < 2; ++mt)
                    #pragma unroll
                    for (int h = 0; h < 2; ++h) {
                        float d0 = fmaf(-2.f, acc[mt][nt][2 * h + 0], e0);
                        float d1 = fmaf(-2.f, acc[mt][nt][2 * h + 1], e1);
                        m1[mt][h] = fminf(m1[mt][h], fminf(d0, d1));
                    }
            }
            #pragma unroll
            for (int mt = 0; mt < 2; ++mt)
                #pragma unroll
                for (int h = 0; h < 2; ++h) {
                    float m = m1[mt][h];
                    m = fminf(m, __shfl_xor_sync(0xffffffffu, m, 1, 4));
                    m = fminf(m, __shfl_xor_sync(0xffffffffu, m, 2, 4));
                    Brun[mt][h] = fminf(Brun[mt][h], m);
                }

            // ---- phase 2: collect d~ <= Brun + W (1 FMA + cmp per code) -----
            #pragma unroll
            for (int nt = 0; nt < 8; ++nt) {
                int cl = pass * 128 + warp_n * 64 + nt * 8 + 2 * t4;
                float e0 = esq_s[cl], e1 = esq_s[cl + 1];
                int c0 = q * 512 + cl;
                #pragma unroll
                for (int mt = 0; mt < 2; ++mt)
                    #pragma unroll
                    for (int h = 0; h < 2; ++h) {
                        float T = Brun[mt][h] + W[mt][h];
                        float d0 = fmaf(-2.f, acc[mt][nt][2 * h + 0], e0);
                        float d1 = fmaf(-2.f, acc[mt][nt][2 * h + 1], e1);
                        if (d0 <= T || d1 <= T) {
                            int tok = row0 + warp_m * 32 + mt * 16 + g4 + 8 * h;
                            if (d0 <= T) {
                                int pos = atomicAdd(&g_cnt[tok], 1);
                                if (pos < CAP) g_cand[tok * CAP + pos] = c0;
                            }
                            if (d1 <= T) {
                                int pos = atomicAdd(&g_cnt[tok], 1);
                                if (pos < CAP) g_cand[tok * CAP + pos] = c0 + 1;
                            }
                        }
                    }
            }
        }
    }
}

// ---------------------------------------------------------------------------
// eval: exact fp32 distance for each candidate; warp per token. Overflow
// (>CAP) falls back to full scan. Deterministic (min dist, tie -> lower idx).
// ---------------------------------------------------------------------------
__global__ void __launch_bounds__(256) eval_kernel(const float* __restrict__ X) {
    int wid = threadIdx.x >> 5, lane = threadIdx.x & 31;
    int tok = blockIdx.x * 8 + wid;

    const float4* xr = (const float4*)(X + (size_t)tok * 256 + lane * 8);
    float4 x0 = xr[0], x1 = xr[1];
    int cnt = g_cnt[tok];
    float best = 3.4e38f;
    int bi = 0x7fffffff;

    int limit = (cnt <= CAP) ? cnt : N_CODE;
    #pragma unroll 1
    for (int c = 0; c < limit; ++c) {
        int code = (cnt <= CAP) ? g_cand[tok * CAP + c] : c;
        const float4* er = (const float4*)(g_embed + (size_t)code * 256 + lane * 8);
        float4 e0 = er[0], e1 = er[1];
        float dot = x0.x * e0.x + x0.y * e0.y + x0.z * e0.z + x0.w * e0.w
                  + x1.x * e1.x + x1.y * e1.y + x1.z * e1.z + x1.w * e1.w;
        #pragma unroll
        for (int off = 16; off > 0; off >>= 1)
            dot += __shfl_xor_sync(0xffffffffu, dot, off);
        float dist = fmaf(-2.f, dot, g_esq[code]);
        if (dist < best || (dist == best && code < bi)) { best = dist; bi = code; }
    }
    if (lane == 0) g_idx[tok] = bi;
}

// ---------------------------------------------------------------------------
__global__ void __launch_bounds__(256) gather_kernel(float* __restrict__ out, int N) {
    int i = blockIdx.x * 256 + threadIdx.x;
    int tok = i >> 6, c4 = i & 63;
    int idx = g_idx[tok];
    float4 v = ((const float4*)g_embed)[(size_t)idx * 64 + c4];
    ((float4*)out)[i] = v;
    if (c4 == 0) out[(size_t)N * D_DIM + tok] = (float)idx;
}

// ---------------------------------------------------------------------------
extern "C" void kernel_launch(void* const* d_in, const int* in_sizes, int n_in,
                              void* d_out, int out_size) {
    const float* X  = (const float*)d_in[0];
    const float* ES = (const float*)d_in[1];
    const float* U  = (const float*)d_in[2];
    float* out = (float*)d_out;
    (void)n_in; (void)out_size;
    int N = in_sizes[0] / D_DIM;   // 32768

    cudaFuncSetAttribute(stageA_kernel,
                         cudaFuncAttributeMaxDynamicSharedMemorySize, SMEM_TOTAL);

    prep_all_kernel<<<N_CODE / 2 + (N / 128) * 4, 256>>>(X, ES, U);
    stageA_kernel<<<(N / 128) * 4, 288, SMEM_TOTAL>>>();
    eval_kernel<<<N / 8, 256>>>(X);
    gather_kernel<<<(N * 64) / 256, 256>>>(out, N);
}

// round 11
// speedup vs baseline: 16.7606x; 16.7606x over previous
#include <cuda_runtime.h>
#include <cuda_fp16.h>
#include <cstdint>

#define D_DIM 256
#define N_TOK 32768
#define N_CODE 2048
#define CAP 96

// ---------------- scratch (static device globals) ---------------------------
__device__ __half g_xhi[N_TOK * D_DIM];   // X hi split, A-fragment order
__device__ __half g_ehi[N_CODE * D_DIM];  // E hi split, B-fragment order
__device__ float  g_embed[N_CODE * D_DIM];// E row-major
__device__ float  g_esq[N_CODE];          // ||e||^2
__device__ float  g_eln[N_CODE];          // ||e_lo||
__device__ float  g_xh2[4 * N_TOK];       // per-(chunk,token) ||x_hi||^2 partials
__device__ float  g_xl2[4 * N_TOK];       // per-(chunk,token) ||x_lo||^2 partials
__device__ int    g_cnt[N_TOK];           // candidate counts
__device__ int    g_cand[N_TOK * CAP];    // candidate code ids
__device__ int    g_idx[N_TOK];           // final indices
__device__ int    g_ovf[N_TOK];           // overflow token list
__device__ int    g_novf;                 // overflow count

// ---------------- helpers ----------------------------------------------------
__device__ __forceinline__ uint32_t smem_u32(const void* p) {
    uint32_t a;
    asm("{ .reg .u64 t; cvta.to.shared.u64 t, %1; cvt.u32.u64 %0, t; }"
        : "=r"(a) : "l"(p));
    return a;
}
__device__ __forceinline__ uint32_t pack2(__half a, __half b) {
    __half2 h2 = __halves2half2(a, b);
    return *reinterpret_cast<uint32_t*>(&h2);
}

#define MBAR_INIT(a, c) asm volatile("mbarrier.init.shared.b64 [%0], %1;" :: "r"(a), "r"((uint32_t)(c)) : "memory")
#define MBAR_EXPECT_TX(a, b) asm volatile("mbarrier.arrive.expect_tx.shared.b64 _, [%0], %1;" :: "r"(a), "r"((uint32_t)(b)) : "memory")
#define MBAR_ARRIVE(a)  asm volatile("mbarrier.arrive.shared.b64 _, [%0];" :: "r"(a) : "memory")

#define MBAR_WAIT(mbar, parity) do {                                          \
    uint32_t _m = (mbar), _ph = (parity), _done;                              \
    asm volatile("{ .reg .pred p; mbarrier.try_wait.parity.acquire.cta.shared::cta.b64 p, [%1], %2; selp.b32 %0, 1, 0, p; }" \
                 : "=r"(_done) : "r"(_m), "r"(_ph) : "memory");               \
    if (!_done) {                                                             \
        asm volatile("{ .reg .pred P1; WL_%=: mbarrier.try_wait.parity.acquire.cta.shared::cta.b64 P1, [%0], %1, 0x989680; @P1 bra.uni WD_%=; bra.uni WL_%=; WD_%=: }" \
                     :: "r"(_m), "r"(_ph) : "memory");                        \
    }                                                                         \
} while (0)

#define BULK_G2S(dst, src, bytes, mbar)                                       \
    asm volatile("cp.async.bulk.shared::cluster.global.mbarrier::complete_tx::bytes [%0], [%1], %2, [%3];" \
                 :: "r"(dst), "l"(src), "r"((uint32_t)(bytes)), "r"(mbar) : "memory")

__device__ __forceinline__ void mma_f16(float* d, const uint32_t* a, const uint32_t* b) {
    asm("mma.sync.aligned.m16n8k16.row.col.f32.f16.f16.f32 "
        "{%0,%1,%2,%3}, {%4,%5,%6,%7}, {%8,%9}, {%0,%1,%2,%3};"
        : "+f"(d[0]), "+f"(d[1]), "+f"(d[2]), "+f"(d[3])
        : "r"(a[0]), "r"(a[1]), "r"(a[2]), "r"(a[3]), "r"(b[0]), "r"(b[1]));
}

// ---------------------------------------------------------------------------
// prep: blocks [0,1024): E prep (2 codes/block). Blocks [1024,2048): X split
// (smem-staged coalesced out) + norm partials + g_cnt zeroing.
// ---------------------------------------------------------------------------
__global__ void __launch_bounds__(256) prep_all_kernel(const float* __restrict__ X,
                                                       const float* __restrict__ embed_sum,
                                                       const float* __restrict__ usage) {
    if (blockIdx.x == 0 && threadIdx.x == 0) g_novf = 0;

    if (blockIdx.x < N_CODE / 2) {
        int t = threadIdx.x;
        int k = blockIdx.x * 2 + (t >> 7);
        int tl = t & 127;
        __shared__ float wq[8], wl[8];

        float u = fmaxf(usage[k], 1e-5f);
        float2 vv = ((const float2*)embed_sum)[k * 128 + tl];
        float v0 = vv.x / u, v1 = vv.y / u;
        ((float2*)g_embed)[k * 128 + tl] = make_float2(v0, v1);

        __half h0 = __float2half_rn(v0);
        __half h1 = __float2half_rn(v1);
        float l0f = v0 - __half2float(h0), l1f = v1 - __half2float(h1);

        int d = 2 * tl;
        int pass = k >> 7, n_in = k & 127;
        int n_tile = n_in >> 3, ncol = n_in & 7;
        int ch = d >> 6, kk = d & 63, ks = kk >> 4, kc = kk & 15;
        int lane = ncol * 4 + ((kc >> 1) & 3);
        int reg = kc >> 3;
        int hbase = (pass * 4 + ch) * 8192 + ((ks * 16 + n_tile) * 32 + lane) * 4 + reg * 2;
        ((uint32_t*)g_ehi)[hbase >> 1] = pack2(h0, h1);

        float sq = v0 * v0 + v1 * v1;
        float sl = l0f * l0f + l1f * l1f;
        #pragma unroll
        for (int off = 16; off > 0; off >>= 1) {
            sq += __shfl_down_sync(0xffffffffu, sq, off);
            sl += __shfl_down_sync(0xffffffffu, sl, off);
        }
        if ((t & 31) == 0) { wq[t >> 5] = sq; wl[t >> 5] = sl; }
        __syncthreads();
        if (tl == 0) {
            int w0 = (t >> 7) * 4;
            g_esq[k] = wq[w0] + wq[w0 + 1] + wq[w0 + 2] + wq[w0 + 3];
            g_eln[k] = sqrtf(wl[w0] + wl[w0 + 1] + wl[w0 + 2] + wl[w0 + 3]);
        }
    } else {
        __shared__ uint32_t sh_hi[4096];
        __shared__ float xa_h[128], xa_l[128];
        int tile = blockIdx.x - N_CODE / 2;
        int m_block = tile >> 2, ch = tile & 3;
        int t = threadIdx.x;
        if (t < 128) { xa_h[t] = 0.f; xa_l[t] = 0.f; }
        if (t < 32) g_cnt[tile * 32 + t] = 0;
        __syncthreads();

        #pragma unroll
        for (int it = 0; it < 8; ++it) {
            int i4 = t + it * 256;
            int tok_l = i4 >> 4;
            int dl4 = i4 & 15;
            float4 x = ((const float4*)X)[(size_t)(m_block * 128 + tok_l) * 64 + ch * 16 + dl4];
            float xv[4] = {x.x, x.y, x.z, x.w};
            int m_tile = tok_l >> 4, r = tok_l & 15;
            float hs = 0.f, ls = 0.f;
            #pragma unroll
            for (int j = 0; j < 4; j += 2) {
                __half ha = __float2half_rn(xv[j]);
                __half hb = __float2half_rn(xv[j + 1]);
                float haf = __half2float(ha), hbf = __half2float(hb);
                float laf = xv[j] - haf, lbf = xv[j + 1] - hbf;
                hs += haf * haf + hbf * hbf;
                ls += laf * laf + lbf * lbf;
                int kk = dl4 * 4 + j;
                int ks = kk >> 4, kc = kk & 15;
                int lane = (r & 7) * 4 + ((kc >> 1) & 3);
                int reg = (r >> 3) | ((kc >> 3) << 1);
                int half_loc = ((ks * 8 + m_tile) * 32 + lane) * 8 + reg * 2;
                sh_hi[half_loc >> 1] = pack2(ha, hb);
            }
            atomicAdd(&xa_h[tok_l], hs);
            atomicAdd(&xa_l[tok_l], ls);
        }
        __syncthreads();

        uint4* dh = (uint4*)(((uint32_t*)g_xhi) + tile * 4096);
        const uint4* sh4 = (const uint4*)sh_hi;
        #pragma unroll
        for (int it = 0; it < 4; ++it)
            dh[t + it * 256] = sh4[t + it * 256];

        if (t < 128) {
            int tok = m_block * 128 + t;
            g_xh2[ch * N_TOK + tok] = xa_h[t];
            g_xl2[ch * N_TOK + tok] = xa_l[t];
        }
    }
}

// ---------------------------------------------------------------------------
// Stage A: hi-only fp16 mma GEMM + certified candidate collection.
// Per code: U_k = xh*A_k + xl*B_k + 1e-3 (A=2||e_lo||+pad, B=2||e||).
// Phase 1 transforms acc in place to (d~ - U) and folds Brun = min(d~ + U).
// Phase 2: compare-only collect (d~ - U <= Brun).
// ---------------------------------------------------------------------------
#define SMEM_TOTAL 122880
#define A_OFF 8192
#define B_OFF 73728

__global__ void __launch_bounds__(288, 1) stageA_kernel() {
    extern __shared__ __align__(1024) char smem[];
    uint32_t sb = smem_u32(smem);
    int tid = threadIdx.x, lane = tid & 31, wid = tid >> 5;
    int mtile = blockIdx.x >> 2, q = blockIdx.x & 3;
    int row0 = mtile * 128;

    const uint32_t AF    = sb + 0;
    const uint32_t FB[3] = {sb + 8,  sb + 16, sb + 24};
    const uint32_t EB[3] = {sb + 32, sb + 40, sb + 48};
    float* esq_s = (float*)(smem + 1024);   // [512]
    float* A_s   = (float*)(smem + 3072);   // [512] 2||e_lo|| + pad*||e||
    float* B_s   = (float*)(smem + 5120);   // [512] 2||e||
    float* xhn_s = (float*)(smem + 7168);   // [128]
    float* xln_s = (float*)(smem + 7680);   // [128]

    if (tid == 0) {
        MBAR_INIT(AF, 1);
        #pragma unroll
        for (int s = 0; s < 3; ++s) { MBAR_INIT(FB[s], 1); MBAR_INIT(EB[s], 8); }
    }
    for (int i = tid; i < 512; i += 288) {
        float e2 = g_esq[q * 512 + i];
        float en = sqrtf(e2);
        esq_s[i] = e2;
        A_s[i] = 2.f * g_eln[q * 512 + i] + 1e-4f * en;   // + fp32 accum pad
        B_s[i] = 2.f * en;
    }
    if (tid < 128) {
        int tok = row0 + tid;
        xhn_s[tid] = sqrtf(g_xh2[tok] + g_xh2[N_TOK + tok] +
                           g_xh2[2 * N_TOK + tok] + g_xh2[3 * N_TOK + tok]);
        xln_s[tid] = sqrtf(g_xl2[tok] + g_xl2[N_TOK + tok] +
                           g_xl2[2 * N_TOK + tok] + g_xl2[3 * N_TOK + tok]);
    }
    __syncthreads();

    if (wid == 8) {
        if (lane == 0) {
            MBAR_EXPECT_TX(AF, 65536);
            #pragma unroll
            for (int ch = 0; ch < 4; ++ch)
                BULK_G2S(sb + A_OFF + ch * 16384,
                         &g_xhi[(mtile * 4 + ch) * 8192], 16384, AF);
            #pragma unroll 1
            for (int g = 0; g < 16; ++g) {
                int s = g % 3;
                if (g >= 3) MBAR_WAIT(EB[s], ((g / 3) + 1) & 1);
                int pass = g >> 2, ch = g & 3;
                MBAR_EXPECT_TX(FB[s], 16384);
                BULK_G2S(sb + B_OFF + s * 16384,
                         &g_ehi[((q * 4 + pass) * 4 + ch) * 8192], 16384, FB[s]);
            }
        }
    } else {
        int warp_m = wid & 3, warp_n = wid >> 2;
        int t4 = lane & 3, g4 = lane >> 2;

        float xh[2][2], xl[2][2], Brun[2][2];
        #pragma unroll
        for (int mt = 0; mt < 2; ++mt)
            #pragma unroll
            for (int h = 0; h < 2; ++h) {
                int tok_l = warp_m * 32 + mt * 16 + g4 + 8 * h;
                xh[mt][h] = xhn_s[tok_l];
                xl[mt][h] = xln_s[tok_l];
                Brun[mt][h] = 3.4e38f;
            }

        MBAR_WAIT(AF, 0);

        #pragma unroll 1
        for (int pass = 0; pass < 4; ++pass) {
            float acc[2][8][4];
            #pragma unroll
            for (int mt = 0; mt < 2; ++mt)
                #pragma unroll
                for (int nt = 0; nt < 8; ++nt)
                    #pragma unroll
                    for (int j = 0; j < 4; ++j) acc[mt][nt][j] = 0.f;

            #pragma unroll 1
            for (int ch = 0; ch < 4; ++ch) {
                int g = pass * 4 + ch;
                int s = g % 3;
                MBAR_WAIT(FB[s], (g / 3) & 1);
                const char* Ah = smem + A_OFF + ch * 16384;
                const char* Bh = smem + B_OFF + s * 16384;
                #pragma unroll
                for (int ks = 0; ks < 4; ++ks) {
                    uint32_t ah[2][4];
                    #pragma unroll
                    for (int mt = 0; mt < 2; ++mt) {
                        int off = ((ks * 8 + warp_m * 2 + mt) * 32 + lane) * 16;
                        *(uint4*)ah[mt] = *(const uint4*)(Ah + off);
                    }
                    uint32_t bh[8][2];
                    #pragma unroll
                    for (int nt = 0; nt < 8; ++nt) {
                        int off = ((ks * 16 + warp_n * 8 + nt) * 32 + lane) * 8;
                        *(uint2*)bh[nt] = *(const uint2*)(Bh + off);
                    }
                    #pragma unroll
                    for (int mt = 0; mt < 2; ++mt)
                        #pragma unroll
                        for (int nt = 0; nt < 8; ++nt)
                            mma_f16(acc[mt][nt], ah[mt], bh[nt]);
                }
                if (lane == 0) MBAR_ARRIVE(EB[s]);
            }

            // ---- phase 1: acc <- (d~ - U) in place; Brun <- min(d~ + U) ----
            float m1[2][2] = {{3.4e38f, 3.4e38f}, {3.4e38f, 3.4e38f}};
            #pragma unroll
            for (int nt = 0; nt < 8; ++nt) {
                int cl = pass * 128 + warp_n * 64 + nt * 8 + 2 * t4;
                float e0 = esq_s[cl], e1 = esq_s[cl + 1];
                float A0 = A_s[cl], A1 = A_s[cl + 1];
                float B0 = B_s[cl], B1 = B_s[cl + 1];
                #pragma unroll
                for (int mt = 0; mt < 2; ++mt)
                    #pragma unroll
                    for (int h = 0; h < 2; ++h) {
                        float u0 = fmaf(xh[mt][h], A0, fmaf(xl[mt][h], B0, 1e-3f));
                        float u1 = fmaf(xh[mt][h], A1, fmaf(xl[mt][h], B1, 1e-3f));
                        float d0 = fmaf(-2.f, acc[mt][nt][2 * h + 0], e0);
                        float d1 = fmaf(-2.f, acc[mt][nt][2 * h + 1], e1);
                        m1[mt][h] = fminf(m1[mt][h], fminf(d0 + u0, d1 + u1));
                        acc[mt][nt][2 * h + 0] = d0 - u0;
                        acc[mt][nt][2 * h + 1] = d1 - u1;
                    }
            }
            #pragma unroll
            for (int mt = 0; mt < 2; ++mt)
                #pragma unroll
                for (int h = 0; h < 2; ++h) {
                    float m = m1[mt][h];
                    m = fminf(m, __shfl_xor_sync(0xffffffffu, m, 1, 4));
                    m = fminf(m, __shfl_xor_sync(0xffffffffu, m, 2, 4));
                    Brun[mt][h] = fminf(Brun[mt][h], m);
                }

            // ---- phase 2: compare-only collect -----------------------------
            #pragma unroll
            for (int nt = 0; nt < 8; ++nt) {
                int c0 = q * 512 + pass * 128 + warp_n * 64 + nt * 8 + 2 * t4;
                #pragma unroll
                for (int mt = 0; mt < 2; ++mt)
                    #pragma unroll
                    for (int h = 0; h < 2; ++h) {
                        float s0 = acc[mt][nt][2 * h + 0];
                        float s1 = acc[mt][nt][2 * h + 1];
                        float T = Brun[mt][h];
                        if (s0 <= T || s1 <= T) {
                            int tok = row0 + warp_m * 32 + mt * 16 + g4 + 8 * h;
                            if (s0 <= T) {
                                int pos = atomicAdd(&g_cnt[tok], 1);
                                if (pos < CAP) g_cand[tok * CAP + pos] = c0;
                            }
                            if (s1 <= T) {
                                int pos = atomicAdd(&g_cnt[tok], 1);
                                if (pos < CAP) g_cand[tok * CAP + pos] = c0 + 1;
                            }
                        }
                    }
            }
        }
    }
}

// ---------------------------------------------------------------------------
// eval: exact fp32 distances for candidates; warp per token. Tokens with
// cnt > CAP are deferred to the block-parallel overflow kernel.
// ---------------------------------------------------------------------------
__global__ void __launch_bounds__(256) eval_kernel(const float* __restrict__ X) {
    int wid = threadIdx.x >> 5, lane = threadIdx.x & 31;
    int tok = blockIdx.x * 8 + wid;

    int cnt = g_cnt[tok];
    if (cnt > CAP) {
        if (lane == 0) {
            int p = atomicAdd(&g_novf, 1);
            g_ovf[p] = tok;
        }
        return;
    }

    const float4* xr = (const float4*)(X + (size_t)tok * 256 + lane * 8);
    float4 x0 = xr[0], x1 = xr[1];
    float best = 3.4e38f;
    int bi = 0x7fffffff;

    #pragma unroll 1
    for (int c = 0; c < cnt; ++c) {
        int code = g_cand[tok * CAP + c];
        const float4* er = (const float4*)(g_embed + (size_t)code * 256 + lane * 8);
        float4 e0 = er[0], e1 = er[1];
        float dot = x0.x * e0.x + x0.y * e0.y + x0.z * e0.z + x0.w * e0.w
                  + x1.x * e1.x + x1.y * e1.y + x1.z * e1.z + x1.w * e1.w;
        #pragma unroll
        for (int off = 16; off > 0; off >>= 1)
            dot += __shfl_xor_sync(0xffffffffu, dot, off);
        float dist = fmaf(-2.f, dot, g_esq[code]);
        if (dist < best || (dist == best && code < bi)) { best = dist; bi = code; }
    }
    if (lane == 0) g_idx[tok] = bi;
}

// ---------------------------------------------------------------------------
// overflow: CTA per flagged token, full exact scan (8 codes/thread),
// block argmin reduce with first-index tie-breaking.
// ---------------------------------------------------------------------------
__global__ void __launch_bounds__(256) overflow_kernel(const float* __restrict__ X) {
    __shared__ float xs[256];
    __shared__ float rd[256];
    __shared__ int   ri[256];
    int tid = threadIdx.x;
    int nf = g_novf;

    for (int w = blockIdx.x; w < nf; w += gridDim.x) {
        int tok = g_ovf[w];
        __syncthreads();
        xs[tid] = X[(size_t)tok * 256 + tid];
        __syncthreads();

        float best = 3.4e38f;
        int bi = 0x7fffffff;
        #pragma unroll 1
        for (int c = tid; c < N_CODE; c += 256) {
            const float4* er = (const float4*)(g_embed + (size_t)c * 256);
            float dot = 0.f;
            #pragma unroll 8
            for (int d4 = 0; d4 < 64; ++d4) {
                float4 ev = er[d4];
                const float* xp = &xs[d4 * 4];
                dot = fmaf(xp[0], ev.x, dot);
                dot = fmaf(xp[1], ev.y, dot);
                dot = fmaf(xp[2], ev.z, dot);
                dot = fmaf(xp[3], ev.w, dot);
            }
            float dist = fmaf(-2.f, dot, g_esq[c]);
            if (dist < best || (dist == best && c < bi)) { best = dist; bi = c; }
        }
        rd[tid] = best; ri[tid] = bi;
        __syncthreads();
        #pragma unroll
        for (int s = 128; s > 0; s >>= 1) {
            if (tid < s) {
                float ob = rd[tid + s]; int obi = ri[tid + s];
                if (ob < rd[tid] || (ob == rd[tid] && obi < ri[tid])) {
                    rd[tid] = ob; ri[tid] = obi;
                }
            }
            __syncthreads();
        }
        if (tid == 0) g_idx[tok] = ri[0];
    }
}

// ---------------------------------------------------------------------------
__global__ void __launch_bounds__(256) gather_kernel(float* __restrict__ out, int N) {
    int i = blockIdx.x * 256 + threadIdx.x;
    int tok = i >> 6, c4 = i & 63;
    int idx = g_idx[tok];
    float4 v = ((const float4*)g_embed)[(size_t)idx * 64 + c4];
    ((float4*)out)[i] = v;
    if (c4 == 0) out[(size_t)N * D_DIM + tok] = (float)idx;
}

// ---------------------------------------------------------------------------
extern "C" void kernel_launch(void* const* d_in, const int* in_sizes, int n_in,
                              void* d_out, int out_size) {
    const float* X  = (const float*)d_in[0];
    const float* ES = (const float*)d_in[1];
    const float* U  = (const float*)d_in[2];
    float* out = (float*)d_out;
    (void)n_in; (void)out_size;
    int N = in_sizes[0] / D_DIM;   // 32768

    cudaFuncSetAttribute(stageA_kernel,
                         cudaFuncAttributeMaxDynamicSharedMemorySize, SMEM_TOTAL);

    prep_all_kernel<<<N_CODE / 2 + (N / 128) * 4, 256>>>(X, ES, U);
    stageA_kernel<<<(N / 128) * 4, 288, SMEM_TOTAL>>>();
    eval_kernel<<<N / 8, 256>>>(X);
    overflow_kernel<<<296, 256>>>(X);
    gather_kernel<<<(N * 64) / 256, 256>>>(out, N);
}

// round 12
// speedup vs baseline: 25.1232x; 1.4989x over previous
#include <cuda_runtime.h>
#include <cuda_fp16.h>
#include <cstdint>

#define D_DIM 256
#define N_TOK 32768
#define N_CODE 2048

// ---------------- scratch (static device globals) ---------------------------
__device__ __half g_xhi[N_TOK * D_DIM];   // X hi split, m16n8k16 A-fragment order
__device__ __half g_xlo[N_TOK * D_DIM];   // X lo split
__device__ __half g_ehi[N_CODE * D_DIM];  // E hi split, B-fragment order
__device__ __half g_elo[N_CODE * D_DIM];  // E lo split
__device__ float  g_embed[N_CODE * D_DIM];// E row-major (gather)
__device__ float  g_esq[N_CODE];          // ||e||^2
__device__ unsigned long long g_key[N_TOK]; // packed (mono(dist)<<32 | code)

// ---------------- helpers ----------------------------------------------------
__device__ __forceinline__ uint32_t smem_u32(const void* p) {
    uint32_t a;
    asm("{ .reg .u64 t; cvta.to.shared.u64 t, %1; cvt.u32.u64 %0, t; }"
        : "=r"(a) : "l"(p));
    return a;
}
__device__ __forceinline__ uint32_t pack2(__half a, __half b) {
    __half2 h2 = __halves2half2(a, b);
    return *reinterpret_cast<uint32_t*>(&h2);
}
// monotone float->uint mapping (preserves total order)
__device__ __forceinline__ uint32_t fmono(float f) {
    uint32_t b = __float_as_uint(f);
    return b ^ ((b & 0x80000000u) ? 0xFFFFFFFFu : 0x80000000u);
}

#define MBAR_INIT(a, c) asm volatile("mbarrier.init.shared.b64 [%0], %1;" :: "r"(a), "r"((uint32_t)(c)) : "memory")
#define MBAR_EXPECT_TX(a, b) asm volatile("mbarrier.arrive.expect_tx.shared.b64 _, [%0], %1;" :: "r"(a), "r"((uint32_t)(b)) : "memory")
#define MBAR_ARRIVE(a)  asm volatile("mbarrier.arrive.shared.b64 _, [%0];" :: "r"(a) : "memory")

#define MBAR_WAIT(mbar, parity) do {                                          \
    uint32_t _m = (mbar), _ph = (parity), _done;                              \
    asm volatile("{ .reg .pred p; mbarrier.try_wait.parity.acquire.cta.shared::cta.b64 p, [%1], %2; selp.b32 %0, 1, 0, p; }" \
                 : "=r"(_done) : "r"(_m), "r"(_ph) : "memory");               \
    if (!_done) {                                                             \
        asm volatile("{ .reg .pred P1; WL_%=: mbarrier.try_wait.parity.acquire.cta.shared::cta.b64 P1, [%0], %1, 0x989680; @P1 bra.uni WD_%=; bra.uni WL_%=; WD_%=: }" \
                     :: "r"(_m), "r"(_ph) : "memory");                        \
    }                                                                         \
} while (0)

#define BULK_G2S(dst, src, bytes, mbar)                                       \
    asm volatile("cp.async.bulk.shared::cluster.global.mbarrier::complete_tx::bytes [%0], [%1], %2, [%3];" \
                 :: "r"(dst), "l"(src), "r"((uint32_t)(bytes)), "r"(mbar) : "memory")

// mma.sync m16n8k16 fp16 -> fp32 accumulate
__device__ __forceinline__ void mma_f16(float* d, const uint32_t* a, const uint32_t* b) {
    asm("mma.sync.aligned.m16n8k16.row.col.f32.f16.f16.f32 "
        "{%0,%1,%2,%3}, {%4,%5,%6,%7}, {%8,%9}, {%0,%1,%2,%3};"
        : "+f"(d[0]), "+f"(d[1]), "+f"(d[2]), "+f"(d[3])
        : "r"(a[0]), "r"(a[1]), "r"(a[2]), "r"(a[3]), "r"(b[0]), "r"(b[1]));
}

// ---------------------------------------------------------------------------
// Fused prep.
// Blocks [0, 1024): E prep, 2 codes per block (256 threads fully used).
// Blocks [1024, 2048): X split for one (m_block, chunk) fragment tile.
//   Two-phase smem staging through ONE 16 KB buffer (hi first, lo values
//   parked in registers) -> halves smem/block vs R7 -> ~2x occupancy.
// ---------------------------------------------------------------------------
__global__ void __launch_bounds__(256) prep_all_kernel(const float* __restrict__ X,
                                                       const float* __restrict__ embed_sum,
                                                       const float* __restrict__ usage) {
    if (blockIdx.x < N_CODE / 2) {
        // -------- E prep: embed, esq, fp16 split in B-fragment order --------
        int t = threadIdx.x;
        int k = blockIdx.x * 2 + (t >> 7);
        int tl = t & 127;
        __shared__ float wsum[8];

        float u = fmaxf(usage[k], 1e-5f);
        float2 vv = ((const float2*)embed_sum)[k * 128 + tl];
        float v0 = vv.x / u, v1 = vv.y / u;
        ((float2*)g_embed)[k * 128 + tl] = make_float2(v0, v1);

        __half h0 = __float2half_rn(v0);
        __half l0 = __float2half_rn(v0 - __half2float(h0));
        __half h1 = __float2half_rn(v1);
        __half l1 = __float2half_rn(v1 - __half2float(h1));

        int d = 2 * tl;
        int pass = k >> 7, n_in = k & 127;
        int n_tile = n_in >> 3, ncol = n_in & 7;
        int ch = d >> 6, kk = d & 63, ks = kk >> 4, kc = kk & 15;
        int lane = ncol * 4 + ((kc >> 1) & 3);
        int reg = kc >> 3;
        int hbase = (pass * 4 + ch) * 8192 + ((ks * 16 + n_tile) * 32 + lane) * 4 + reg * 2;
        ((uint32_t*)g_ehi)[hbase >> 1] = pack2(h0, h1);
        ((uint32_t*)g_elo)[hbase >> 1] = pack2(l0, l1);

        float val = v0 * v0 + v1 * v1;
        #pragma unroll
        for (int off = 16; off > 0; off >>= 1)
            val += __shfl_down_sync(0xffffffffu, val, off);
        if ((t & 31) == 0) wsum[t >> 5] = val;
        __syncthreads();
        if (tl == 0) {
            int w0 = (t >> 7) * 4;
            g_esq[k] = wsum[w0] + wsum[w0 + 1] + wsum[w0 + 2] + wsum[w0 + 3];
        }
    } else {
        // -------- X split: two-phase 16 KB smem stage, coalesced out ---------
        __shared__ uint32_t sh[4096];   // 16 KB, reused for hi then lo
        int tile = blockIdx.x - N_CODE / 2;     // 0..1023
        int m_block = tile >> 2, ch = tile & 3;
        int t = threadIdx.x;

        if (ch == 0 && t < 128) g_key[m_block * 128 + t] = 0xFFFFFFFFFFFFFFFFull;

        uint32_t lo_keep[16];
        int loc_keep[8];

        #pragma unroll
        for (int it = 0; it < 8; ++it) {
            int i4 = t + it * 256;                 // 0..2047 tile-local float4
            int tok_l = i4 >> 4;                   // 0..127
            int dl4 = i4 & 15;                     // float4 within 64-d chunk
            float4 x = ((const float4*)X)[(size_t)(m_block * 128 + tok_l) * 64 + ch * 16 + dl4];
            float xv[4] = {x.x, x.y, x.z, x.w};
            int m_tile = tok_l >> 4, r = tok_l & 15;
            #pragma unroll
            for (int j = 0; j < 4; j += 2) {
                __half ha = __float2half_rn(xv[j]);
                __half la = __float2half_rn(xv[j] - __half2float(ha));
                __half hb = __float2half_rn(xv[j + 1]);
                __half lb = __float2half_rn(xv[j + 1] - __half2float(hb));
                int kk = dl4 * 4 + j;              // 0..63 within chunk
                int ks = kk >> 4, kc = kk & 15;
                int lane = (r & 7) * 4 + ((kc >> 1) & 3);
                int reg = (r >> 3) | ((kc >> 3) << 1);
                int half_loc = ((ks * 8 + m_tile) * 32 + lane) * 8 + reg * 2;
                sh[half_loc >> 1] = pack2(ha, hb);
                lo_keep[it * 2 + (j >> 1)] = pack2(la, lb);
                if (j == 0) loc_keep[it] = half_loc >> 1;   // second pair is +? recompute below
            }
        }
        __syncthreads();

        // write hi out (coalesced uint4)
        {
            uint4* dh = (uint4*)(((uint32_t*)g_xhi) + tile * 4096);
            const uint4* s4 = (const uint4*)sh;
            #pragma unroll
            for (int it = 0; it < 4; ++it)
                dh[t + it * 256] = s4[t + it * 256];
        }
        __syncthreads();

        // phase 2: stage lo from registers (recompute the second pair's loc)
        #pragma unroll
        for (int it = 0; it < 8; ++it) {
            int i4 = t + it * 256;
            int tok_l = i4 >> 4;
            int dl4 = i4 & 15;
            int m_tile = tok_l >> 4, r = tok_l & 15;
            #pragma unroll
            for (int j = 0; j < 4; j += 2) {
                int kk = dl4 * 4 + j;
                int ks = kk >> 4, kc = kk & 15;
                int lane = (r & 7) * 4 + ((kc >> 1) & 3);
                int reg = (r >> 3) | ((kc >> 3) << 1);
                int half_loc = ((ks * 8 + m_tile) * 32 + lane) * 8 + reg * 2;
                sh[half_loc >> 1] = lo_keep[it * 2 + (j >> 1)];
            }
            (void)loc_keep;
        }
        __syncthreads();

        {
            uint4* dl = (uint4*)(((uint32_t*)g_xlo) + tile * 4096);
            const uint4* s4 = (const uint4*)sh;
            #pragma unroll
            for (int it = 0; it < 4; ++it)
                dl[t + it * 256] = s4[t + it * 256];
        }
    }
}

// ---------------------------------------------------------------------------
// Fused fp16x2 mma.sync GEMM + argmin over an (m-tile 128, n-quarter 512) unit.
// Grid: 1024 CTAs = 256 m-tiles x 4 quarters. 288 threads = 8 compute + 1 prod.
// A (xhi+xlo, 128 KB) persistent in SMEM (loaded once); B rings through
// 3 x 32 KB stages. 4 passes x 128 codes, K=256 in 4 chunks of 64.
// SMEM: [0..64) mbarriers | [1024..3072) esq | [3072..134144) A | 3 B stages.
// ---------------------------------------------------------------------------
#define SMEM_TOTAL 232448
#define A_OFF 3072
#define B_OFF 134144

__global__ void __launch_bounds__(288, 1) argmin_mma_kernel() {
    extern __shared__ __align__(1024) char smem[];
    uint32_t sb = smem_u32(smem);
    int tid = threadIdx.x, lane = tid & 31, wid = tid >> 5;
    int mtile = blockIdx.x >> 2, q = blockIdx.x & 3;

    const uint32_t AF    = sb + 0;
    const uint32_t FB[3] = {sb + 8,  sb + 16, sb + 24};
    const uint32_t EB[3] = {sb + 32, sb + 40, sb + 48};
    float* esq_s = (float*)(smem + 1024);   // [512] quarter esq

    if (tid == 0) {
        MBAR_INIT(AF, 1);
        #pragma unroll
        for (int s = 0; s < 3; ++s) { MBAR_INIT(FB[s], 1); MBAR_INIT(EB[s], 8); }
    }
    for (int i = tid; i < 512; i += 288) esq_s[i] = g_esq[q * 512 + i];
    __syncthreads();

    int row0 = mtile * 128;

    if (wid == 8) {
        // ---------------- dedicated producer warp ---------------------------
        if (lane == 0) {
            // A: load once (4 chunks x (hi 16K + lo 16K))
            MBAR_EXPECT_TX(AF, 131072);
            #pragma unroll
            for (int ch = 0; ch < 4; ++ch) {
                BULK_G2S(sb + A_OFF + ch * 32768,
                         &g_xhi[(mtile * 4 + ch) * 8192], 16384, AF);
                BULK_G2S(sb + A_OFF + ch * 32768 + 16384,
                         &g_xlo[(mtile * 4 + ch) * 8192], 16384, AF);
            }
            // B stream: 16 chunk tiles
            #pragma unroll 1
            for (int g = 0; g < 16; ++g) {
                int s = g % 3;
                if (g >= 3) MBAR_WAIT(EB[s], ((g / 3) + 1) & 1);
                int pass = g >> 2, ch = g & 3;
                uint32_t st = sb + B_OFF + s * 32768;
                MBAR_EXPECT_TX(FB[s], 32768);
                BULK_G2S(st,         &g_ehi[((q * 4 + pass) * 4 + ch) * 8192], 16384, FB[s]);
                BULK_G2S(st + 16384, &g_elo[((q * 4 + pass) * 4 + ch) * 8192], 16384, FB[s]);
            }
        }
    } else {
        // ---------------- 8 compute warps ------------------------------------
        int warp_m = wid & 3, warp_n = wid >> 2;
        int t4 = lane & 3, g4 = lane >> 2;

        float best[2][2];
        int bestI[2][2];
        #pragma unroll
        for (int a = 0; a < 2; ++a)
            #pragma unroll
            for (int b = 0; b < 2; ++b) { best[a][b] = 3.4e38f; bestI[a][b] = 0; }

        MBAR_WAIT(AF, 0);   // A resident for whole kernel

        #pragma unroll 1
        for (int pass = 0; pass < 4; ++pass) {
            float acc[2][8][4];
            #pragma unroll
            for (int mt = 0; mt < 2; ++mt)
                #pragma unroll
                for (int nt = 0; nt < 8; ++nt)
                    #pragma unroll
                    for (int j = 0; j < 4; ++j) acc[mt][nt][j] = 0.f;

            #pragma unroll 1
            for (int ch = 0; ch < 4; ++ch) {
                int g = pass * 4 + ch;
                int s = g % 3;
                MBAR_WAIT(FB[s], (g / 3) & 1);

                const char* Ah = smem + A_OFF + ch * 32768;
                const char* Al = Ah + 16384;
                const char* Bh = smem + B_OFF + s * 32768;
                const char* Bl = Bh + 16384;

                #pragma unroll
                for (int ks = 0; ks < 4; ++ks) {
                    uint32_t ah[2][4], al[2][4];
                    #pragma unroll
                    for (int mt = 0; mt < 2; ++mt) {
                        int off = ((ks * 8 + warp_m * 2 + mt) * 32 + lane) * 16;
                        *(uint4*)ah[mt] = *(const uint4*)(Ah + off);
                        *(uint4*)al[mt] = *(const uint4*)(Al + off);
                    }
                    uint32_t bh[8][2], bl[8][2];
                    #pragma unroll
                    for (int nt = 0; nt < 8; ++nt) {
                        int off = ((ks * 16 + warp_n * 8 + nt) * 32 + lane) * 8;
                        *(uint2*)bh[nt] = *(const uint2*)(Bh + off);
                        *(uint2*)bl[nt] = *(const uint2*)(Bl + off);
                    }
                    // term-ordered: hi*hi, hi*lo, lo*hi
                    #pragma unroll
                    for (int mt = 0; mt < 2; ++mt)
                        #pragma unroll
                        for (int nt = 0; nt < 8; ++nt)
                            mma_f16(acc[mt][nt], ah[mt], bh[nt]);
                    #pragma unroll
                    for (int mt = 0; mt < 2; ++mt)
                        #pragma unroll
                        for (int nt = 0; nt < 8; ++nt)
                            mma_f16(acc[mt][nt], ah[mt], bl[nt]);
                    #pragma unroll
                    for (int mt = 0; mt < 2; ++mt)
                        #pragma unroll
                        for (int nt = 0; nt < 8; ++nt)
                            mma_f16(acc[mt][nt], al[mt], bh[nt]);
                }
                if (lane == 0) MBAR_ARRIVE(EB[s]);
            }

            // fold pass into running argmin: dist = esq - 2*dot
            #pragma unroll
            for (int nt = 0; nt < 8; ++nt) {
                int clocal = pass * 128 + warp_n * 64 + nt * 8 + 2 * t4;
                float e0 = esq_s[clocal], e1 = esq_s[clocal + 1];
                int cbase = q * 512 + clocal;
                #pragma unroll
                for (int mt = 0; mt < 2; ++mt) {
                    float d0v = fmaf(-2.f, acc[mt][nt][0], e0);
                    if (d0v < best[mt][0]) { best[mt][0] = d0v; bestI[mt][0] = cbase; }
                    float d1v = fmaf(-2.f, acc[mt][nt][1], e1);
                    if (d1v < best[mt][0]) { best[mt][0] = d1v; bestI[mt][0] = cbase + 1; }
                    float d2v = fmaf(-2.f, acc[mt][nt][2], e0);
                    if (d2v < best[mt][1]) { best[mt][1] = d2v; bestI[mt][1] = cbase; }
                    float d3v = fmaf(-2.f, acc[mt][nt][3], e1);
                    if (d3v < best[mt][1]) { best[mt][1] = d3v; bestI[mt][1] = cbase + 1; }
                }
            }
        }

        // width-4 shuffle reduce, then global atomic merge
        #pragma unroll
        for (int mt = 0; mt < 2; ++mt)
            #pragma unroll
            for (int h = 0; h < 2; ++h) {
                float b = best[mt][h];
                int bi = bestI[mt][h];
                #pragma unroll
                for (int off = 2; off > 0; off >>= 1) {
                    float ob = __shfl_down_sync(0xffffffffu, b, off, 4);
                    int obi = __shfl_down_sync(0xffffffffu, bi, off, 4);
                    if (ob < b || (ob == b && obi < bi)) { b = ob; bi = obi; }
                }
                if (t4 == 0) {
                    int tok = row0 + warp_m * 32 + mt * 16 + g4 + 8 * h;
                    unsigned long long key =
                        ((unsigned long long)fmono(b) << 32) | (uint32_t)bi;
                    atomicMin(&g_key[tok], key);
                }
            }
    }
}

// ---------------------------------------------------------------------------
// gather: one thread per (token, float4 chunk). 8192 CTAs x 256 threads.
// ---------------------------------------------------------------------------
__global__ void __launch_bounds__(256) gather_kernel(float* __restrict__ out, int N) {
    int i = blockIdx.x * 256 + threadIdx.x;     // [0, N*64)
    int tok = i >> 6, c4 = i & 63;
    int idx = (int)(g_key[tok] & 0xFFFFFFFFull);
    float4 v = ((const float4*)g_embed)[(size_t)idx * 64 + c4];
    ((float4*)out)[i] = v;
    if (c4 == 0) out[(size_t)N * D_DIM + tok] = (float)idx;
}

// ---------------------------------------------------------------------------
extern "C" void kernel_launch(void* const* d_in, const int* in_sizes, int n_in,
                              void* d_out, int out_size) {
    const float* X  = (const float*)d_in[0];
    const float* ES = (const float*)d_in[1];
    const float* U  = (const float*)d_in[2];
    float* out = (float*)d_out;
    (void)n_in; (void)out_size;
    int N = in_sizes[0] / D_DIM;   // 32768

    cudaFuncSetAttribute(argmin_mma_kernel,
                         cudaFuncAttributeMaxDynamicSharedMemorySize, SMEM_TOTAL);

    prep_all_kernel<<<N_CODE / 2 + (N / 128) * 4, 256>>>(X, ES, U);
    argmin_mma_kernel<<<(N / 128) * 4, 288, SMEM_TOTAL>>>();
    gather_kernel<<<(N * 64) / 256, 256>>>(out, N);
}